// round 2
// baseline (speedup 1.0000x reference)
#include <cuda_runtime.h>
#include <math.h>

namespace {
constexpr int Bn = 8, Cn = 4, Hn = 256, Wn = 256;
constexpr int NPIX = Bn * Hn * Wn;  // 524288
constexpr int NBLK = NPIX / 256;    // 2048
}

__device__ double g_acc;        // zero-initialized at module load
__device__ unsigned g_count;    // zero-initialized at module load

__device__ __forceinline__ int ld_mask(const int* __restrict__ m, int idx, int is64) {
    return __ldg(m + (idx << is64));
}

// Exact vertical 1D distance at (h, w) for class c: smallest k>=1 with a
// background pixel (mask != c) at h-k or h+k; 512 if the column has none.
__device__ __forceinline__ int vdist(const int* __restrict__ m, int base,
                                     int h, int w, int c, int is64) {
#pragma unroll 1
    for (int k = 1; k < Hn; ++k) {
        int up = h - k, dn = h + k;
        bool hit = false;
        if (up >= 0) hit = (ld_mask(m, base + up * Wn + w, is64) != c);
        if (dn < Hn) hit = hit || (ld_mask(m, base + dn * Wn + w, is64) != c);
        if (hit) return k;
        if (up <= 0 && dn >= Hn - 1) return 512;
    }
    return 512;
}

__global__ void boundary_loss_kernel(const float* __restrict__ pred,
                                     const int* __restrict__ mask,
                                     float* __restrict__ out, int out_n) {
    // ---- per-warp int64/int32 detection (2 cache lines, broadcast) ----
    const int lane = threadIdx.x & 31;
    const int probe = __ldg(mask + 2 * lane + 1);
    const int is64 = __all_sync(0xFFFFFFFFu, probe == 0) ? 1 : 0;

    const int tid = blockIdx.x * blockDim.x + threadIdx.x;  // 0..NPIX-1
    const int w = tid & (Wn - 1);
    const int h = (tid >> 8) & (Hn - 1);
    const int b = tid >> 16;
    const int base = b * (Hn * Wn);

    float term = 0.0f;
    const int c = ld_mask(mask, base + h * Wn + w, is64);
    if (c != 0) {
        int g0 = vdist(mask, base, h, w, c, is64);
        float m = (float)(g0 * g0);

        // Exact lower-envelope min with outward pruning: remaining candidates
        // at radius r have value >= r*r, so stop once r*r >= m.
#pragma unroll 1
        for (int r = 1; r < Wn; ++r) {
            float r2 = (float)(r * r);
            if (r2 >= m) break;
            int xl = w - r, xr = w + r;
            if (xl < 0 && xr >= Wn) break;
            if (xl >= 0) {
                float g2p = 0.0f;
                if (ld_mask(mask, base + h * Wn + xl, is64) == c) {
                    int gv = vdist(mask, base, h, xl, c, is64);
                    g2p = (float)(gv * gv);
                }
                m = fminf(m, g2p + r2);
            }
            if (xr < Wn) {
                float g2p = 0.0f;
                if (ld_mask(mask, base + h * Wn + xr, is64) == c) {
                    int gv = vdist(mask, base, h, xr, c, is64);
                    g2p = (float)(gv * gv);
                }
                m = fminf(m, g2p + r2);
            }
        }

        const float norm = (float)(sqrt((double)(Hn * Hn + Wn * Wn)) + 1e-6);
        float dist = sqrtf(m) / norm;
        term = __ldg(&pred[((b * Cn + c) * Hn + h) * Wn + w]) * dist;
    }

    // ---- block reduction ----
#pragma unroll
    for (int o = 16; o > 0; o >>= 1)
        term += __shfl_down_sync(0xFFFFFFFFu, term, o);

    __shared__ float ws[8];
    __shared__ bool s_last;
    if (lane == 0) ws[threadIdx.x >> 5] = term;
    __syncthreads();
    if (threadIdx.x < 8) {
        float v = ws[threadIdx.x];
#pragma unroll
        for (int o = 4; o > 0; o >>= 1)
            v += __shfl_down_sync(0xFFu, v, o);
        if (threadIdx.x == 0) atomicAdd(&g_acc, (double)v);
    }

    // ---- last-block finalize (self-resetting for graph replay) ----
    __threadfence();
    if (threadIdx.x == 0) {
        unsigned prev = atomicAdd(&g_count, 1u);
        s_last = (prev == (unsigned)(gridDim.x - 1));
    }
    __syncthreads();
    if (s_last) {
        if (threadIdx.x == 0) {
            double total = g_acc;
            float v = (float)(total / ((double)NPIX * (Cn - 1)));
            for (int i = 0; i < out_n; ++i) out[i] = v;
            g_acc = 0.0;      // reset for next (deterministic) replay
            g_count = 0u;
        }
    }
}

extern "C" void kernel_launch(void* const* d_in, const int* in_sizes, int n_in,
                              void* d_out, int out_size) {
    const float* pred;
    const int* mask;
    if (in_sizes[0] >= in_sizes[1]) {
        pred = (const float*)d_in[0];
        mask = (const int*)d_in[1];
    } else {
        pred = (const float*)d_in[1];
        mask = (const int*)d_in[0];
    }
    boundary_loss_kernel<<<NBLK, 256>>>(pred, mask, (float*)d_out, out_size);
}

// round 3
// speedup vs baseline: 1.1911x; 1.1911x over previous
#include <cuda_runtime.h>
#include <math.h>

namespace {
constexpr int Bn = 8, Cn = 4, Hn = 256, Wn = 256;
constexpr int NPIX = Bn * Hn * Wn;  // 524288
constexpr int NBLK = NPIX / 256;    // 2048 (one block == one image row)
}

__device__ double g_acc;      // zero-init at module load; self-reset each run
__device__ unsigned g_count;  // zero-init at module load; self-reset each run

__device__ __forceinline__ int ld_mask(const int* __restrict__ m, int idx, int is64) {
    return __ldg(m + (idx << is64));
}

__global__ void boundary_loss_kernel(const float* __restrict__ pred,
                                     const int* __restrict__ mask,
                                     float* __restrict__ out, int out_n) {
    __shared__ int s_mask[Wn];
    __shared__ float s_g2[Wn];
    __shared__ float ws[8];
    __shared__ bool s_last;

    // ---- per-warp int64/int32 detection (2 broadcast cache lines) ----
    const int lane = threadIdx.x & 31;
    const int probe = __ldg(mask + 2 * lane + 1);
    const int is64 = __all_sync(0xFFFFFFFFu, probe == 0) ? 1 : 0;

    const int tid = blockIdx.x * blockDim.x + threadIdx.x;
    const int w = threadIdx.x;          // blockDim == Wn == 256
    const int h = (tid >> 8) & (Hn - 1);
    const int b = tid >> 16;
    const int base = b * (Hn * Wn);
    const int rowbase = base + h * Wn;

    // ---- stage this row's mask + per-column vertical distance^2 in shared ----
    const int c = ld_mask(mask, rowbase + w, is64);
    s_mask[w] = c;

    float g2 = 0.0f;
    if (c != 0) {
        // smallest k>=1 with mask(h±k, w) != c; 512 if column has no background.
        int g0 = 512;
#pragma unroll 1
        for (int k = 1; k < Hn; ++k) {
            int up = h - k, dn = h + k;
            bool hit = false;
            if (up >= 0) hit = (ld_mask(mask, base + up * Wn + w, is64) != c);
            if (dn < Hn) hit = hit || (ld_mask(mask, base + dn * Wn + w, is64) != c);
            if (hit) { g0 = k; break; }
            if (up <= 0 && dn >= Hn - 1) break;
        }
        g2 = (float)(g0 * g0);
    }
    s_g2[w] = g2;
    __syncthreads();

    // ---- exact horizontal lower envelope, entirely from shared ----
    float term = 0.0f;
    if (c != 0) {
        float m = g2;  // candidate x' = x
#pragma unroll 1
        for (int r = 1; r < Wn; ++r) {
            float r2 = (float)(r * r);
            if (r2 >= m) break;
            int xl = w - r, xr = w + r;
            if (xl < 0 && xr >= Wn) break;
            if (xl >= 0) {
                float g2p = (s_mask[xl] == c) ? s_g2[xl] : 0.0f;
                m = fminf(m, g2p + r2);
            }
            if (xr < Wn) {
                float g2p = (s_mask[xr] == c) ? s_g2[xr] : 0.0f;
                m = fminf(m, g2p + r2);
            }
        }
        const float norm = (float)(sqrt((double)(Hn * Hn + Wn * Wn)) + 1e-6);
        float dist = sqrtf(m) / norm;
        term = __ldg(&pred[((b * Cn + c) * Hn + h) * Wn + w]) * dist;
    }

    // ---- block reduction ----
#pragma unroll
    for (int o = 16; o > 0; o >>= 1)
        term += __shfl_down_sync(0xFFFFFFFFu, term, o);
    if (lane == 0) ws[threadIdx.x >> 5] = term;
    __syncthreads();
    if (threadIdx.x < 8) {
        float v = ws[threadIdx.x];
#pragma unroll
        for (int o = 4; o > 0; o >>= 1)
            v += __shfl_down_sync(0xFFu, v, o);
        if (threadIdx.x == 0) {
            atomicAdd(&g_acc, (double)v);
            __threadfence();  // order g_acc before g_count (thread 0 only)
            unsigned prev = atomicAdd(&g_count, 1u);
            s_last = (prev == (unsigned)(gridDim.x - 1));
        }
    }
    __syncthreads();

    // ---- last-block finalize (self-resetting for graph replay) ----
    if (s_last && threadIdx.x == 0) {
        double total = g_acc;
        float v = (float)(total / ((double)NPIX * (Cn - 1)));
        for (int i = 0; i < out_n; ++i) out[i] = v;
        g_acc = 0.0;
        g_count = 0u;
    }
}

extern "C" void kernel_launch(void* const* d_in, const int* in_sizes, int n_in,
                              void* d_out, int out_size) {
    const float* pred;
    const int* mask;
    if (in_sizes[0] >= in_sizes[1]) {
        pred = (const float*)d_in[0];
        mask = (const int*)d_in[1];
    } else {
        pred = (const float*)d_in[1];
        mask = (const int*)d_in[0];
    }
    boundary_loss_kernel<<<NBLK, 256>>>(pred, mask, (float*)d_out, out_size);
}

// round 4
// speedup vs baseline: 1.3137x; 1.1029x over previous
#include <cuda_runtime.h>
#include <math.h>

namespace {
constexpr int Bn = 8, Cn = 4, Hn = 256, Wn = 256;
constexpr int NPIX = Bn * Hn * Wn;  // 524288
constexpr int NBLK = NPIX / 256;    // 2048 (one block == one image row)
}

__device__ double g_acc;      // zero-init at module load; self-reset each run
__device__ unsigned g_count;  // zero-init at module load; self-reset each run

__device__ __forceinline__ int ld_mask(const int* __restrict__ m, int idx, int is64) {
    return __ldg(m + (idx << is64));
}

__global__ void boundary_loss_kernel(const float* __restrict__ pred,
                                     const int* __restrict__ mask,
                                     float* __restrict__ out, int out_n) {
    __shared__ int s_mask[Wn];
    __shared__ float s_g2[Wn];
    __shared__ float ws[8];

    // ---- per-warp int64/int32 detection (2 broadcast cache lines) ----
    const int lane = threadIdx.x & 31;
    const int probe = __ldg(mask + 2 * lane + 1);
    const int is64 = __all_sync(0xFFFFFFFFu, probe == 0) ? 1 : 0;

    const int tid = blockIdx.x * blockDim.x + threadIdx.x;
    const int w = threadIdx.x;          // blockDim == Wn == 256
    const int h = (tid >> 8) & (Hn - 1);
    const int b = tid >> 16;
    const int base = b * (Hn * Wn);

    // ---- own-column mask + vertical distance (batched, MLP=8 per round) ----
    const int c = ld_mask(mask, base + h * Wn + w, is64);
    s_mask[w] = c;

    float g2 = 0.0f;
    if (c != 0) {
        const int lim_u = h;            // max k upward
        const int lim_d = Hn - 1 - h;   // max k downward
        const int lim = (lim_u > lim_d) ? lim_u : lim_d;
        int g0 = 512;
#pragma unroll 1
        for (int kb = 1; kb <= lim; kb += 4) {
            // issue all 8 probes (predicated) before any compare
            int u0 = (kb + 0 <= lim_u) ? ld_mask(mask, base + (h - kb - 0) * Wn + w, is64) : c;
            int d0 = (kb + 0 <= lim_d) ? ld_mask(mask, base + (h + kb + 0) * Wn + w, is64) : c;
            int u1 = (kb + 1 <= lim_u) ? ld_mask(mask, base + (h - kb - 1) * Wn + w, is64) : c;
            int d1 = (kb + 1 <= lim_d) ? ld_mask(mask, base + (h + kb + 1) * Wn + w, is64) : c;
            int u2 = (kb + 2 <= lim_u) ? ld_mask(mask, base + (h - kb - 2) * Wn + w, is64) : c;
            int d2 = (kb + 2 <= lim_d) ? ld_mask(mask, base + (h + kb + 2) * Wn + w, is64) : c;
            int u3 = (kb + 3 <= lim_u) ? ld_mask(mask, base + (h - kb - 3) * Wn + w, is64) : c;
            int d3 = (kb + 3 <= lim_d) ? ld_mask(mask, base + (h + kb + 3) * Wn + w, is64) : c;
            if (u0 != c || d0 != c) { g0 = kb; break; }
            if (u1 != c || d1 != c) { g0 = kb + 1; break; }
            if (u2 != c || d2 != c) { g0 = kb + 2; break; }
            if (u3 != c || d3 != c) { g0 = kb + 3; break; }
        }
        g2 = (float)(g0 * g0);
    }
    s_g2[w] = g2;

    // prefetch pred gather (latency overlaps the envelope loop below)
    float p = 0.0f;
    if (c != 0) p = __ldg(&pred[((b * Cn + c) * Hn + h) * Wn + w]);

    __syncthreads();

    // ---- exact horizontal lower envelope from shared ----
    float term = 0.0f;
    if (c != 0) {
        float m = g2;  // candidate x' = x
#pragma unroll 1
        for (int r = 1; r < Wn; ++r) {
            float r2 = (float)(r * r);
            if (r2 >= m) break;
            int xl = w - r, xr = w + r;
            if (xl < 0 && xr >= Wn) break;
            if (xl >= 0) {
                float g2p = (s_mask[xl] == c) ? s_g2[xl] : 0.0f;
                m = fminf(m, g2p + r2);
            }
            if (xr < Wn) {
                float g2p = (s_mask[xr] == c) ? s_g2[xr] : 0.0f;
                m = fminf(m, g2p + r2);
            }
        }
        const float norm = (float)(sqrt((double)(Hn * Hn + Wn * Wn)) + 1e-6);
        term = p * (sqrtf(m) / norm);
    }

    // ---- block reduction ----
#pragma unroll
    for (int o = 16; o > 0; o >>= 1)
        term += __shfl_down_sync(0xFFFFFFFFu, term, o);
    if (lane == 0) ws[threadIdx.x >> 5] = term;
    __syncthreads();
    if (threadIdx.x < 8) {
        float v = ws[threadIdx.x];
#pragma unroll
        for (int o = 4; o > 0; o >>= 1)
            v += __shfl_down_sync(0xFFu, v, o);
        if (threadIdx.x == 0) {
            atomicAdd(&g_acc, (double)v);
            __threadfence();  // order my g_acc add before my g_count bump
            unsigned prev = atomicAdd(&g_count, 1u);
            if (prev == (unsigned)(gridDim.x - 1)) {
                // all 2048 g_acc adds are L2-visible (each fenced before count)
                double total = atomicAdd(&g_acc, 0.0);
                float r = (float)(total / ((double)NPIX * (Cn - 1)));
                for (int i = 0; i < out_n; ++i) out[i] = r;
                g_acc = 0.0;   // reset for next graph replay (deterministic)
                g_count = 0u;
            }
        }
    }
}

extern "C" void kernel_launch(void* const* d_in, const int* in_sizes, int n_in,
                              void* d_out, int out_size) {
    const float* pred;
    const int* mask;
    if (in_sizes[0] >= in_sizes[1]) {
        pred = (const float*)d_in[0];
        mask = (const int*)d_in[1];
    } else {
        pred = (const float*)d_in[1];
        mask = (const int*)d_in[0];
    }
    boundary_loss_kernel<<<NBLK, 256>>>(pred, mask, (float*)d_out, out_size);
}

// round 5
// speedup vs baseline: 1.3434x; 1.0226x over previous
#include <cuda_runtime.h>
#include <math.h>

namespace {
constexpr int Bn = 8, Cn = 4, Hn = 256, Wn = 256;
constexpr int NPIX = Bn * Hn * Wn;  // 524288
constexpr int NBLK = NPIX / 256;    // 2048 (one block == one image row)
}

__device__ double g_acc;      // zero-init at module load; self-reset each run
__device__ unsigned g_count;

__global__ void boundary_loss_kernel(const float* __restrict__ pred,
                                     const int* __restrict__ mask,
                                     float* __restrict__ out, int out_n) {
    __shared__ int s_pk[Wn];   // (class << 20) | g0^2   (g0^2 <= 2^18)
    __shared__ float ws[8];

    const int lane = threadIdx.x & 31;
    const int tid = blockIdx.x * blockDim.x + threadIdx.x;
    const int w = threadIdx.x;          // blockDim == Wn == 256
    const int h = (tid >> 8) & (Hn - 1);
    const int b = tid >> 16;
    const int base = b * (Hn * Wn);
    const int idx0 = base + h * Wn + w;
    const int lim_u = h, lim_d = Hn - 1 - h;

    // ---- round 1: one MLP batch; every address is dtype-width independent
    //      or safe under int32 interpretation (word index < NPIX <= buffer words).
    const int probe = __ldg(mask + 2 * lane + 1);   // is64 detector
    int mv[9];
    mv[0] = __ldg(mask + idx0);                     // own mask (int32 interp)
#pragma unroll
    for (int j = 1; j <= 4; ++j) {
        mv[j]     = (j <= lim_u) ? __ldg(mask + idx0 - j * Wn) : -1;
        mv[4 + j] = (j <= lim_d) ? __ldg(mask + idx0 + j * Wn) : -1;
    }
    const int pbase = (b * Cn) * Hn * Wn + h * Wn + w;
    const float p1 = __ldg(pred + pbase + 1 * Hn * Wn);
    const float p2 = __ldg(pred + pbase + 2 * Hn * Wn);
    const float p3 = __ldg(pred + pbase + 3 * Hn * Wn);

    // values 0..3 stored as int64 => every odd 32-bit word is zero (fp prob 4^-32)
    const int is64 = __all_sync(0xFFFFFFFFu, probe == 0) ? 1 : 0;
    if (is64) {  // uniform branch; extra round only when data really is int64
        mv[0] = __ldg(mask + 2 * idx0);
#pragma unroll
        for (int j = 1; j <= 4; ++j) {
            mv[j]     = (j <= lim_u) ? __ldg(mask + 2 * (idx0 - j * Wn)) : -1;
            mv[4 + j] = (j <= lim_d) ? __ldg(mask + 2 * (idx0 + j * Wn)) : -1;
        }
    }

    // ---- resolve vertical distance from the batch (k<=4 covers ~99.998%) ----
    const int c = mv[0];
    int pk = 0;
    float g2 = 0.0f;
    if (c != 0) {
        int g0 = 512;
        bool done = false;
#pragma unroll
        for (int j = 1; j <= 4; ++j) {
            bool hit = (mv[j] != -1 && mv[j] != c) || (mv[4 + j] != -1 && mv[4 + j] != c);
            if (!done && hit) { g0 = j; done = true; }
        }
        if (!done) {  // rare deep scan, batched 8 loads per round
            const int lim = (lim_u > lim_d) ? lim_u : lim_d;
#pragma unroll 1
            for (int kb = 5; kb <= lim && !done; kb += 4) {
                int u[4], d[4];
#pragma unroll
                for (int j = 0; j < 4; ++j) {
                    int k = kb + j;
                    u[j] = (k <= lim_u) ? __ldg(mask + ((idx0 - k * Wn) << is64)) : c;
                    d[j] = (k <= lim_d) ? __ldg(mask + ((idx0 + k * Wn) << is64)) : c;
                }
#pragma unroll
                for (int j = 0; j < 4; ++j)
                    if (!done && (u[j] != c || d[j] != c)) { g0 = kb + j; done = true; }
            }
        }
        g2 = (float)(g0 * g0);
        pk = (c << 20) | (g0 * g0);
    }
    s_pk[w] = pk;
    __syncthreads();

    // ---- exact horizontal lower envelope (shared, 4 radii per round) ----
    float term = 0.0f;
    if (c != 0) {
        float m = g2;
#pragma unroll 1
        for (int rb = 1; rb < Wn; rb += 4) {
            if ((float)(rb * rb) >= m) break;
#pragma unroll
            for (int j = 0; j < 4; ++j) {
                int r = rb + j;
                float r2 = (float)(r * r);
                int xl = w - r, xr = w + r;
                int pl = s_pk[(xl >= 0) ? xl : 0];
                int pr = s_pk[(xr < Wn) ? xr : (Wn - 1)];
                float gl = ((pl >> 20) == c) ? (float)(pl & 0xFFFFF) : 0.0f;
                float gr = ((pr >> 20) == c) ? (float)(pr & 0xFFFFF) : 0.0f;
                float cl = (xl >= 0) ? gl + r2 : 1e30f;
                float cr = (xr < Wn) ? gr + r2 : 1e30f;
                m = fminf(m, fminf(cl, cr));
            }
        }
        const float norm = (float)(sqrt((double)(Hn * Hn + Wn * Wn)) + 1e-6);
        float p = (c == 1) ? p1 : ((c == 2) ? p2 : p3);
        term = p * (sqrtf(m) / norm);
    }

    // ---- block reduction + last-block finalize ----
#pragma unroll
    for (int o = 16; o > 0; o >>= 1)
        term += __shfl_down_sync(0xFFFFFFFFu, term, o);
    if (lane == 0) ws[threadIdx.x >> 5] = term;
    __syncthreads();
    if (threadIdx.x < 8) {
        float v = ws[threadIdx.x];
#pragma unroll
        for (int o = 4; o > 0; o >>= 1)
            v += __shfl_down_sync(0xFFu, v, o);
        if (threadIdx.x == 0) {
            atomicAdd(&g_acc, (double)v);
            __threadfence();  // order my g_acc add before my g_count bump
            unsigned prev = atomicAdd(&g_count, 1u);
            if (prev == (unsigned)(gridDim.x - 1)) {
                double total = atomicAdd(&g_acc, 0.0);  // L2-coherent read
                float r = (float)(total / ((double)NPIX * (Cn - 1)));
                for (int i = 0; i < out_n; ++i) out[i] = r;
                g_acc = 0.0;   // reset for next graph replay (deterministic)
                g_count = 0u;
            }
        }
    }
}

extern "C" void kernel_launch(void* const* d_in, const int* in_sizes, int n_in,
                              void* d_out, int out_size) {
    const float* pred;
    const int* mask;
    if (in_sizes[0] >= in_sizes[1]) {
        pred = (const float*)d_in[0];
        mask = (const int*)d_in[1];
    } else {
        pred = (const float*)d_in[1];
        mask = (const int*)d_in[0];
    }
    boundary_loss_kernel<<<NBLK, 256>>>(pred, mask, (float*)d_out, out_size);
}

// round 6
// speedup vs baseline: 1.3501x; 1.0050x over previous
#include <cuda_runtime.h>
#include <math.h>

namespace {
constexpr int Bn = 8, Cn = 4, Hn = 256, Wn = 256;
constexpr int NPIX = Bn * Hn * Wn;   // 524288
constexpr int PAD = 32;
constexpr int WP = Wn + 2 * PAD;     // 320 (multiple of 32 -> conflict-free)
constexpr int ROWS = 2;              // rows per block
constexpr int TPB = ROWS * Wn;       // 512
constexpr int NBLK = NPIX / TPB;     // 1024
}

__device__ double g_acc;      // zero-init at module load; self-reset each run
__device__ unsigned g_count;

__global__ void boundary_loss_kernel(const float* __restrict__ pred,
                                     const int* __restrict__ mask,
                                     float* __restrict__ out, int out_n) {
    __shared__ float s_e[ROWS][3][WP];  // per-class envelope source, padded 1e30
    __shared__ float ws[TPB / 32];

    const int lane = threadIdx.x & 31;
    const int w = threadIdx.x & (Wn - 1);
    const int row = threadIdx.x >> 8;                 // 0..ROWS-1
    const int grow = blockIdx.x * ROWS + row;         // global row id
    const int b = grow >> 8;
    const int h = grow & (Hn - 1);
    const int base = b * (Hn * Wn);
    const int idx0 = base + h * Wn + w;

    // ---- pad init (1e30 excludes OOB candidates exactly) ----
    if (w < 3 * 2 * PAD) {             // 192 threads per row
        int k = w / (2 * PAD);
        int p = w % (2 * PAD);
        int pos = (p < PAD) ? p : (PAD + Wn + (p - PAD));
        s_e[row][k][pos] = 1e30f;
    }

    // ---- single MLP round: is64 probe, own+8 vertical mask words, 3 preds.
    //      int32 interpretation is always in-bounds (word idx < NPIX). ----
    const int probe = __ldg(mask + 2 * lane + 1);
    int c = __ldg(mask + idx0);
    int u[4], d[4];
#pragma unroll
    for (int j = 1; j <= 4; ++j) {
        int hu = (j <= h) ? h - j : h;          // clamp -> reads c (no hit)
        int hd = (h + j < Hn) ? h + j : h;
        u[j - 1] = __ldg(mask + base + hu * Wn + w);
        d[j - 1] = __ldg(mask + base + hd * Wn + w);
    }
    const int pbase = (b * Cn) * Hn * Wn + h * Wn + w;
    const float p1 = __ldg(pred + pbase + 1 * Hn * Wn);
    const float p2 = __ldg(pred + pbase + 2 * Hn * Wn);
    const float p3 = __ldg(pred + pbase + 3 * Hn * Wn);

    // int64 storage => all odd 32-bit words zero (fp prob 4^-32): reload.
    const int is64 = __all_sync(0xFFFFFFFFu, probe == 0) ? 1 : 0;
    if (is64) {
        c = __ldg(mask + 2 * idx0);
#pragma unroll
        for (int j = 1; j <= 4; ++j) {
            int hu = (j <= h) ? h - j : h;
            int hd = (h + j < Hn) ? h + j : h;
            u[j - 1] = __ldg(mask + 2 * (base + hu * Wn + w));
            d[j - 1] = __ldg(mask + 2 * (base + hd * Wn + w));
        }
    }

    // ---- vertical distance: bitmask + ffs over k=1..4; rare deep scan ----
    float g2 = 0.0f;
    if (c != 0) {
        int bits = 0;
#pragma unroll
        for (int j = 0; j < 4; ++j)
            bits |= ((u[j] != c) | (d[j] != c)) << j;
        int g0;
        if (bits) {
            g0 = __ffs(bits);
        } else {
            g0 = 512;
            const int lim_u = h, lim_d = Hn - 1 - h;
            const int lim = (lim_u > lim_d) ? lim_u : lim_d;
            bool done = false;
#pragma unroll 1
            for (int kb = 5; kb <= lim && !done; kb += 4) {
                int uu[4], dd[4];
#pragma unroll
                for (int j = 0; j < 4; ++j) {
                    int k = kb + j;
                    int hu = (k <= lim_u) ? h - k : h;
                    int hd = (k <= lim_d) ? h + k : h;
                    uu[j] = __ldg(mask + ((base + hu * Wn + w) << is64));
                    dd[j] = __ldg(mask + ((base + hd * Wn + w) << is64));
                }
#pragma unroll
                for (int j = 0; j < 4; ++j)
                    if (!done && (uu[j] != c || dd[j] != c)) { g0 = kb + j; done = true; }
            }
        }
        g2 = (float)(g0 * g0);
    }

    // ---- publish per-class envelope sources ----
    s_e[row][0][PAD + w] = (c == 1) ? g2 : 0.0f;
    s_e[row][1][PAD + w] = (c == 2) ? g2 : 0.0f;
    s_e[row][2][PAD + w] = (c == 3) ? g2 : 0.0f;
    __syncthreads();

    // ---- exact horizontal lower envelope ----
    float term = 0.0f;
    if (c != 0) {
        const float* e = &s_e[row][c - 1][PAD + w];
        float m = g2;
#pragma unroll 1
        for (int rb = 1; rb + 3 <= PAD; rb += 4) {  // unchecked r<=32 (padded)
            float rf = (float)rb;
            if (rf * rf >= m) break;
#pragma unroll
            for (int j = 0; j < 4; ++j) {
                float r = rf + (float)j;
                float r2 = r * r;
                int ri = rb + j;
                m = fminf(m, e[-ri] + r2);
                m = fminf(m, e[ri] + r2);
            }
        }
        if (m > (float)(PAD * PAD)) {  // unresolved beyond r=32: checked scan
#pragma unroll 1
            for (int r = PAD + 1; r < Wn; ++r) {
                float r2 = (float)(r * r);
                if (r2 >= m) break;
                int xl = w - r, xr = w + r;
                if (xl < 0 && xr >= Wn) break;
                if (xl >= 0) m = fminf(m, e[-r] + r2);   // e is padded only +-32;
                if (xr < Wn) m = fminf(m, e[r] + r2);    // xl/xr checks keep in-bounds
            }
        }
        const float norm = (float)(sqrt((double)(Hn * Hn + Wn * Wn)) + 1e-6);
        float p = (c == 1) ? p1 : ((c == 2) ? p2 : p3);
        term = p * (sqrtf(m) / norm);
    }

    // ---- block reduction + last-block finalize ----
#pragma unroll
    for (int o = 16; o > 0; o >>= 1)
        term += __shfl_down_sync(0xFFFFFFFFu, term, o);
    if (lane == 0) ws[threadIdx.x >> 5] = term;
    __syncthreads();
    if (threadIdx.x < TPB / 32) {
        float v = ws[threadIdx.x];
#pragma unroll
        for (int o = 8; o > 0; o >>= 1)
            v += __shfl_down_sync(0xFFFFu, v, o);
        if (threadIdx.x == 0) {
            atomicAdd(&g_acc, (double)v);
            __threadfence();  // order my g_acc add before my g_count bump
            unsigned prev = atomicAdd(&g_count, 1u);
            if (prev == (unsigned)(gridDim.x - 1)) {
                double total = atomicAdd(&g_acc, 0.0);  // L2-coherent read
                float r = (float)(total / ((double)NPIX * (Cn - 1)));
                for (int i = 0; i < out_n; ++i) out[i] = r;
                g_acc = 0.0;   // reset for next graph replay (deterministic)
                g_count = 0u;
            }
        }
    }
}

extern "C" void kernel_launch(void* const* d_in, const int* in_sizes, int n_in,
                              void* d_out, int out_size) {
    const float* pred;
    const int* mask;
    if (in_sizes[0] >= in_sizes[1]) {
        pred = (const float*)d_in[0];
        mask = (const int*)d_in[1];
    } else {
        pred = (const float*)d_in[1];
        mask = (const int*)d_in[0];
    }
    boundary_loss_kernel<<<NBLK, TPB>>>(pred, mask, (float*)d_out, out_size);
}

// round 7
// speedup vs baseline: 1.5627x; 1.1574x over previous
#include <cuda_runtime.h>
#include <math.h>

namespace {
constexpr int Bn = 8, Cn = 4, Hn = 256, Wn = 256;
constexpr int NPIX = Bn * Hn * Wn;   // 524288
constexpr int PAD = 32;
constexpr int WP = Wn + 2 * PAD;     // 320
constexpr int TPB = 256;
constexpr int NBLK = NPIX / (2 * TPB);  // 1024 (one block == 2 image rows)
}

__device__ double g_acc;      // zero-init at module load; self-reset each run
__device__ unsigned g_count;

__device__ __forceinline__ int deep_vdist(const int* __restrict__ mask, int base,
                                          int h, int w, int c, int is64) {
    int g0 = 512;
    const int lim_u = h, lim_d = Hn - 1 - h;
    const int lim = (lim_u > lim_d) ? lim_u : lim_d;
    bool done = false;
#pragma unroll 1
    for (int kb = 5; kb <= lim && !done; kb += 4) {
        int uu[4], dd[4];
#pragma unroll
        for (int j = 0; j < 4; ++j) {
            int k = kb + j;
            int hu = (k <= lim_u) ? h - k : h;
            int hd = (k <= lim_d) ? h + k : h;
            uu[j] = __ldg(mask + ((base + hu * Wn + w) << is64));
            dd[j] = __ldg(mask + ((base + hd * Wn + w) << is64));
        }
#pragma unroll
        for (int j = 0; j < 4; ++j)
            if (!done && (uu[j] != c || dd[j] != c)) { g0 = kb + j; done = true; }
    }
    return g0;
}

__device__ __forceinline__ float envelope(const float* __restrict__ e, int w, float g2) {
    float m = g2;
#pragma unroll 1
    for (int rb = 1; rb + 3 <= PAD; rb += 4) {  // unchecked r<=32 (1e30 padded)
        float rf = (float)rb;
        if (rf * rf >= m) break;
#pragma unroll
        for (int j = 0; j < 4; ++j) {
            float r = rf + (float)j;
            float r2 = r * r;
            int ri = rb + j;
            m = fminf(m, e[-ri] + r2);
            m = fminf(m, e[ri] + r2);
        }
    }
    if (m > (float)(PAD * PAD)) {  // exact: unresolved => all r<=32 cands >= m
#pragma unroll 1
        for (int r = PAD + 1; r < Wn; ++r) {
            float r2 = (float)(r * r);
            if (r2 >= m) break;
            int xl = w - r, xr = w + r;
            if (xl < 0 && xr >= Wn) break;
            if (xl >= 0) m = fminf(m, e[-r] + r2);
            if (xr < Wn) m = fminf(m, e[r] + r2);
        }
    }
    return m;
}

__global__ __launch_bounds__(TPB, 8)
void boundary_loss_kernel(const float* __restrict__ pred,
                          const int* __restrict__ mask,
                          float* __restrict__ out, int out_n) {
    __shared__ float s_e[2][3][WP];   // per-row, per-class envelope source
    __shared__ float ws[TPB / 32];

    const int lane = threadIdx.x & 31;
    const int w = threadIdx.x;                 // TPB == Wn
    const int b = blockIdx.x >> 7;             // 128 row-pairs per image
    const int hA = (blockIdx.x & 127) * 2;     // even row
    const int hB = hA + 1;
    const int base = b * (Hn * Wn);

    // ---- pad init: 2 rows x 3 classes x 64 pad entries = 384 ----
#pragma unroll
    for (int i = threadIdx.x; i < 384; i += TPB) {
        int row = i / 192, rem = i % 192;
        int k = rem / 64, p = rem % 64;
        int pos = (p < PAD) ? p : (PAD + Wn + (p - PAD));
        s_e[row][k][pos] = 1e30f;
    }

    // ---- one MLP round: is64 probe + 10-row window (covers both pixels) ----
    const int probe = __ldg(mask + 2 * lane + 1);
    int arr[10];                                // rows hA-4 .. hA+5, clamped
#pragma unroll
    for (int i = 0; i < 10; ++i) {
        int hr = hA - 4 + i;
        hr = (hr < 0) ? 0 : ((hr > Hn - 1) ? Hn - 1 : hr);
        arr[i] = __ldg(mask + base + hr * Wn + w);
    }
    const int is64 = __all_sync(0xFFFFFFFFu, probe == 0) ? 1 : 0;
    if (is64) {   // int64 storage (all odd words zero, fp prob 4^-32): reload
#pragma unroll
        for (int i = 0; i < 10; ++i) {
            int hr = hA - 4 + i;
            hr = (hr < 0) ? 0 : ((hr > Hn - 1) ? Hn - 1 : hr);
            arr[i] = __ldg(mask + 2 * (base + hr * Wn + w));
        }
    }
    const int cA = arr[4];
    const int cB = arr[5];

    // class-directed pred loads (consumed last; latency hides under envelope)
    const int ppix = b * Cn * Hn * Wn + w;
    float pA = 0.0f, pB = 0.0f;
    if (cA != 0) pA = __ldg(pred + ppix + (cA * Hn + hA) * Wn);
    if (cB != 0) pB = __ldg(pred + ppix + (cB * Hn + hB) * Wn);

    // ---- vertical distances from the window (k<=4), rare deep fallback ----
    float g2A = 0.0f, g2B = 0.0f;
    if (cA != 0) {
        int bits = 0;
#pragma unroll
        for (int j = 1; j <= 4; ++j) {
            int uv = (j <= hA) ? arr[4 - j] : cA;
            int dv = (hA + j < Hn) ? arr[4 + j] : cA;
            bits |= ((uv != cA) | (dv != cA)) << (j - 1);
        }
        int g0 = bits ? __ffs(bits) : deep_vdist(mask, base, hA, w, cA, is64);
        g2A = (float)(g0 * g0);
    }
    if (cB != 0) {
        int bits = 0;
#pragma unroll
        for (int j = 1; j <= 4; ++j) {
            int uv = (j <= hB) ? arr[5 - j] : cB;
            int dv = (hB + j < Hn) ? arr[5 + j] : cB;
            bits |= ((uv != cB) | (dv != cB)) << (j - 1);
        }
        int g0 = bits ? __ffs(bits) : deep_vdist(mask, base, hB, w, cB, is64);
        g2B = (float)(g0 * g0);
    }

    // ---- publish envelope sources ----
    s_e[0][0][PAD + w] = (cA == 1) ? g2A : 0.0f;
    s_e[0][1][PAD + w] = (cA == 2) ? g2A : 0.0f;
    s_e[0][2][PAD + w] = (cA == 3) ? g2A : 0.0f;
    s_e[1][0][PAD + w] = (cB == 1) ? g2B : 0.0f;
    s_e[1][1][PAD + w] = (cB == 2) ? g2B : 0.0f;
    s_e[1][2][PAD + w] = (cB == 3) ? g2B : 0.0f;
    __syncthreads();

    // ---- exact horizontal lower envelopes ----
    const float norm = (float)(sqrt((double)(Hn * Hn + Wn * Wn)) + 1e-6);
    float term = 0.0f;
    if (cA != 0) {
        float m = envelope(&s_e[0][cA - 1][PAD + w], w, g2A);
        term += pA * (sqrtf(m) / norm);
    }
    if (cB != 0) {
        float m = envelope(&s_e[1][cB - 1][PAD + w], w, g2B);
        term += pB * (sqrtf(m) / norm);
    }

    // ---- block reduction + last-block finalize ----
#pragma unroll
    for (int o = 16; o > 0; o >>= 1)
        term += __shfl_down_sync(0xFFFFFFFFu, term, o);
    if (lane == 0) ws[threadIdx.x >> 5] = term;
    __syncthreads();
    if (threadIdx.x < TPB / 32) {
        float v = ws[threadIdx.x];
#pragma unroll
        for (int o = 4; o > 0; o >>= 1)
            v += __shfl_down_sync(0xFFu, v, o);
        if (threadIdx.x == 0) {
            atomicAdd(&g_acc, (double)v);
            __threadfence();  // order my g_acc add before my g_count bump
            unsigned prev = atomicAdd(&g_count, 1u);
            if (prev == (unsigned)(gridDim.x - 1)) {
                double total = atomicAdd(&g_acc, 0.0);  // L2-coherent read
                float r = (float)(total / ((double)NPIX * (Cn - 1)));
                for (int i = 0; i < out_n; ++i) out[i] = r;
                g_acc = 0.0;   // reset for next graph replay (deterministic)
                g_count = 0u;
            }
        }
    }
}

extern "C" void kernel_launch(void* const* d_in, const int* in_sizes, int n_in,
                              void* d_out, int out_size) {
    const float* pred;
    const int* mask;
    if (in_sizes[0] >= in_sizes[1]) {
        pred = (const float*)d_in[0];
        mask = (const int*)d_in[1];
    } else {
        pred = (const float*)d_in[1];
        mask = (const int*)d_in[0];
    }
    boundary_loss_kernel<<<NBLK, TPB>>>(pred, mask, (float*)d_out, out_size);
}